// round 1
// baseline (speedup 1.0000x reference)
#include <cuda_runtime.h>

// Problem constants (fixed by the dataset's setup_inputs)
#define BQ 2048      // queries
#define DIM 768      // embedding dim
#define NPAS 16384   // passages = BQ * 8
#define NCB 128      // number of 128-wide column blocks (16384/128)

#define ALPHA_C 2.6f
#define OPT_RANK 1.0f
#define SIGMA_C 1.8f

// Scratch (static device allocations are allowed; cudaMalloc is not)
__device__ float g_starget[BQ];
__device__ float g_smax[BQ * NCB];
__device__ float g_ssum[BQ * NCB];
__device__ int   g_cnt[BQ * NCB];
__device__ float g_rowloss[BQ];

// ---------------------------------------------------------------------------
// Kernel 1: s_target[i] = dot(q[i], p[i*8])   (one warp per row)
// ---------------------------------------------------------------------------
__global__ void target_kernel(const float* __restrict__ q,
                              const float* __restrict__ p) {
    int w = (blockIdx.x * blockDim.x + threadIdx.x) >> 5;
    int lane = threadIdx.x & 31;
    if (w >= BQ) return;
    const float* qr = q + (size_t)w * DIM;
    const float* pr = p + (size_t)(w * 8) * DIM;
    float s = 0.f;
    #pragma unroll 4
    for (int k = lane; k < DIM; k += 32) s = fmaf(qr[k], pr[k], s);
    #pragma unroll
    for (int o = 16; o > 0; o >>= 1) s += __shfl_down_sync(0xffffffffu, s, o);
    if (lane == 0) g_starget[w] = s;
}

// ---------------------------------------------------------------------------
// Kernel 2: 128x128 score tile per block (8x8 microtile, BK=32), fused
// per-(row, colblock) partial reduction: max, sum(exp), rank counts.
// grid = (NCB, BQ/128), block = 256 threads (16x16)
// ---------------------------------------------------------------------------
__global__ __launch_bounds__(256, 2)
void score_partial_kernel(const float* __restrict__ q,
                          const float* __restrict__ p) {
    __shared__ float As[32][132];   // [k][m], pad 4 -> conflict-light transposed store,
    __shared__ float Bs[32][132];   // row stride 528B (16B multiple) -> float4 loads OK
    __shared__ float red[128 * 17];
    __shared__ float rowM[128];

    const int cb = blockIdx.x;     // column block 0..127
    const int rb = blockIdx.y;     // row block    0..15
    const int tid = threadIdx.x;
    const int tx = tid & 15;
    const int ty = tid >> 4;

    float acc[8][8];
    #pragma unroll
    for (int i = 0; i < 8; i++)
        #pragma unroll
        for (int j = 0; j < 8; j++) acc[i][j] = 0.f;

    const float* qB = q + (size_t)(rb * 128) * DIM;
    const float* pB = p + (size_t)(cb * 128) * DIM;

    for (int kt = 0; kt < DIM; kt += 32) {
        // Load 128x32 tiles of A and B (row-major global) into transposed smem.
        #pragma unroll
        for (int r = 0; r < 4; r++) {
            int f  = tid + 256 * r;     // 0..1023 float4 slots
            int m  = f >> 3;            // row within tile
            int k0 = (f & 7) << 2;      // k offset
            float4 va = *(const float4*)(qB + (size_t)m * DIM + kt + k0);
            As[k0 + 0][m] = va.x; As[k0 + 1][m] = va.y;
            As[k0 + 2][m] = va.z; As[k0 + 3][m] = va.w;
            float4 vb = *(const float4*)(pB + (size_t)m * DIM + kt + k0);
            Bs[k0 + 0][m] = vb.x; Bs[k0 + 1][m] = vb.y;
            Bs[k0 + 2][m] = vb.z; Bs[k0 + 3][m] = vb.w;
        }
        __syncthreads();

        #pragma unroll
        for (int k = 0; k < 32; k++) {
            float a[8], b[8];
            *(float4*)(a)     = *(const float4*)&As[k][ty * 8];
            *(float4*)(a + 4) = *(const float4*)&As[k][ty * 8 + 4];
            *(float4*)(b)     = *(const float4*)&Bs[k][tx * 8];
            *(float4*)(b + 4) = *(const float4*)&Bs[k][tx * 8 + 4];
            #pragma unroll
            for (int i = 0; i < 8; i++)
                #pragma unroll
                for (int j = 0; j < 8; j++)
                    acc[i][j] = fmaf(a[i], b[j], acc[i][j]);
        }
        __syncthreads();
    }

    // ---- Fused epilogue: per-row (over this 128-col tile) partials ----
    // Step 1: per-thread row max over its 8 columns
    float rmax[8];
    #pragma unroll
    for (int i = 0; i < 8; i++) {
        float m = acc[i][0];
        #pragma unroll
        for (int j = 1; j < 8; j++) m = fmaxf(m, acc[i][j]);
        rmax[i] = m;
        red[(ty * 8 + i) * 17 + tx] = m;
    }
    __syncthreads();

    // Step 2: tile-local row max (over 16 tx partials)
    if (tid < 128) {
        float m = red[tid * 17];
        #pragma unroll
        for (int t = 1; t < 16; t++) m = fmaxf(m, red[tid * 17 + t]);
        rowM[tid] = m;
    }
    __syncthreads();

    // Step 3: sum(exp) with skip threshold + rank counts
    float sv[8];
    int   cv[8];
    #pragma unroll
    for (int i = 0; i < 8; i++) {
        int rowg = rb * 128 + ty * 8 + i;
        float st = g_starget[rowg];
        float M  = rowM[ty * 8 + i];
        float s = 0.f;
        if (rmax[i] > M - 15.f) {    // exp(<-15) contributes <3e-7 each: negligible
            #pragma unroll
            for (int j = 0; j < 8; j++) s += __expf(acc[i][j] - M);
        }
        sv[i] = s;
        int tcol = rowg * 8;         // positive passage column for this row
        int cg = 0, ce = 0;
        #pragma unroll
        for (int j = 0; j < 8; j++) {
            int col = cb * 128 + tx * 8 + j;
            if (acc[i][j] > st && col != tcol) cg++;       // strictly greater
            if (acc[i][j] == st && col < tcol) ce++;       // stable-sort ties before
        }
        cv[i] = cg | (ce << 16);
    }

    // Pass A: reduce sums
    #pragma unroll
    for (int i = 0; i < 8; i++) red[(ty * 8 + i) * 17 + tx] = sv[i];
    __syncthreads();
    if (tid < 128) {
        float s = 0.f;
        #pragma unroll
        for (int t = 0; t < 16; t++) s += red[tid * 17 + t];
        int idx = (rb * 128 + tid) * NCB + cb;
        g_smax[idx] = rowM[tid];
        g_ssum[idx] = s;
    }
    __syncthreads();

    // Pass B: reduce packed counts
    int* redi = (int*)red;
    #pragma unroll
    for (int i = 0; i < 8; i++) redi[(ty * 8 + i) * 17 + tx] = cv[i];
    __syncthreads();
    if (tid < 128) {
        int c = 0;
        #pragma unroll
        for (int t = 0; t < 16; t++) c += redi[tid * 17 + t];
        g_cnt[(rb * 128 + tid) * NCB + cb] = c;
    }
}

// ---------------------------------------------------------------------------
// Kernel 3: merge NCB partials per row -> per-row weighted loss
// grid = BQ blocks, 128 threads
// ---------------------------------------------------------------------------
__global__ void combine_kernel() {
    __shared__ float sh[128];
    __shared__ int   shi[128];
    int row = blockIdx.x;
    int t = threadIdx.x;
    int idx = row * NCB + t;
    float mx = g_smax[idx];
    float su = g_ssum[idx];
    int   cn = g_cnt[idx];

    sh[t] = mx; __syncthreads();
    for (int o = 64; o > 0; o >>= 1) {
        if (t < o) sh[t] = fmaxf(sh[t], sh[t + o]);
        __syncthreads();
    }
    float M = sh[0]; __syncthreads();

    sh[t] = su * expf(mx - M); __syncthreads();
    for (int o = 64; o > 0; o >>= 1) {
        if (t < o) sh[t] += sh[t + o];
        __syncthreads();
    }
    float S = sh[0];

    shi[t] = cn; __syncthreads();
    for (int o = 64; o > 0; o >>= 1) {
        if (t < o) shi[t] += shi[t + o];
        __syncthreads();
    }

    if (t == 0) {
        int c = shi[0];
        float rank = (float)((c & 0xffff) + (c >> 16));
        float raw = logf(S) + M - g_starget[row];
        float dr = rank - OPT_RANK;
        float w = 1.0f + ALPHA_C * expf(-(dr * dr) / (2.0f * SIGMA_C * SIGMA_C));
        g_rowloss[row] = raw * w;
    }
}

// ---------------------------------------------------------------------------
// Kernel 4: mean over rows -> scalar output
// ---------------------------------------------------------------------------
__global__ void finalize_kernel(float* __restrict__ out) {
    __shared__ float sh[256];
    int t = threadIdx.x;
    float s = 0.f;
    for (int i = t; i < BQ; i += 256) s += g_rowloss[i];
    sh[t] = s; __syncthreads();
    for (int o = 128; o > 0; o >>= 1) {
        if (t < o) sh[t] += sh[t + o];
        __syncthreads();
    }
    if (t == 0) out[0] = sh[0] / (float)BQ;
}

// ---------------------------------------------------------------------------
extern "C" void kernel_launch(void* const* d_in, const int* in_sizes, int n_in,
                              void* d_out, int out_size) {
    const float* q = (const float*)d_in[0];   // [2048, 768] fp32
    const float* p = (const float*)d_in[1];   // [16384, 768] fp32
    float* out = (float*)d_out;               // scalar fp32

    target_kernel<<<BQ / 8, 256>>>(q, p);
    dim3 grid(NCB, BQ / 128);
    score_partial_kernel<<<grid, 256>>>(q, p);
    combine_kernel<<<BQ, 128>>>();
    finalize_kernel<<<1, 256>>>(out);
}

// round 3
// speedup vs baseline: 5.1348x; 5.1348x over previous
#include <cuda_runtime.h>
#include <cuda_bf16.h>
#include <stdint.h>

// Problem constants
#define BQ 2048       // queries (rows)
#define DIM 768       // embedding dim
#define NPAS 16384    // passages (cols)
#define NB32 512      // 32-col partial blocks per row
#define ALPHA_C 2.6f
#define OPT_RANK 1.0f
#define SIGMA_C 1.8f

// Static device scratch (allocation-free)
__device__ __align__(16) __nv_bfloat16 g_qbf[BQ * DIM];
__device__ __align__(16) __nv_bfloat16 g_pbf[NPAS * DIM];
__device__ __align__(16) __nv_bfloat16 g_sc[(size_t)BQ * NPAS];   // 64MB scores
__device__ float g_starget[BQ];
__device__ float g_smax[BQ * NB32];
__device__ int   g_cnt[BQ * NB32];
__device__ float g_rowloss[BQ];

// ---------------------------------------------------------------------------
// PTX helpers (all plain sm_80+ PTX; no arch-feature-gated instructions)
// ---------------------------------------------------------------------------
__device__ __forceinline__ uint32_t smem_u32(const void* p) {
    uint32_t a;
    asm("{ .reg .u64 t; cvta.to.shared.u64 t, %1; cvt.u32.u64 %0, t; }"
        : "=r"(a) : "l"(p));
    return a;
}
__device__ __forceinline__ void cp16(uint32_t dst, const void* src) {
    asm volatile("cp.async.cg.shared.global [%0], [%1], 16;"
                 :: "r"(dst), "l"(src) : "memory");
}
#define CP_COMMIT() asm volatile("cp.async.commit_group;" ::: "memory")
#define CP_WAIT1()  asm volatile("cp.async.wait_group 1;" ::: "memory")
#define CP_WAIT0()  asm volatile("cp.async.wait_group 0;" ::: "memory")

#define LDSM4(r0, r1, r2, r3, addr) \
    asm volatile("ldmatrix.sync.aligned.m8n8.x4.shared.b16 {%0,%1,%2,%3}, [%4];" \
                 : "=r"(r0), "=r"(r1), "=r"(r2), "=r"(r3) : "r"(addr))

#define MMA16816(c, a0, a1, a2, a3, b0, b1) \
    asm volatile("mma.sync.aligned.m16n8k16.row.col.f32.bf16.bf16.f32 " \
                 "{%0,%1,%2,%3}, {%4,%5,%6,%7}, {%8,%9}, {%0,%1,%2,%3};" \
                 : "+f"((c)[0]), "+f"((c)[1]), "+f"((c)[2]), "+f"((c)[3]) \
                 : "r"(a0), "r"(a1), "r"(a2), "r"(a3), "r"(b0), "r"(b1))

// ---------------------------------------------------------------------------
// Kernel 0: fp32 -> bf16 conversion (8 elems / thread)
// ---------------------------------------------------------------------------
__global__ void convert_kernel(const float* __restrict__ q,
                               const float* __restrict__ p) {
    size_t i = ((size_t)blockIdx.x * blockDim.x + threadIdx.x) * 8;
    const size_t nq = (size_t)BQ * DIM;
    const float* src;
    __nv_bfloat16* dst;
    if (i < nq) { src = q + i; dst = g_qbf + i; }
    else        { size_t j = i - nq; src = p + j; dst = g_pbf + j; }
    float4 a = *(const float4*)(src);
    float4 b = *(const float4*)(src + 4);
    __nv_bfloat162 v0 = __floats2bfloat162_rn(a.x, a.y);
    __nv_bfloat162 v1 = __floats2bfloat162_rn(a.z, a.w);
    __nv_bfloat162 v2 = __floats2bfloat162_rn(b.x, b.y);
    __nv_bfloat162 v3 = __floats2bfloat162_rn(b.z, b.w);
    uint4 u;
    u.x = *(uint32_t*)&v0; u.y = *(uint32_t*)&v1;
    u.z = *(uint32_t*)&v2; u.w = *(uint32_t*)&v3;
    *(uint4*)dst = u;
}

// ---------------------------------------------------------------------------
// Kernel 1: exact fp32 s_target[i] = dot(q[i], p[8i])   (one warp per row)
// ---------------------------------------------------------------------------
__global__ void target_kernel(const float* __restrict__ q,
                              const float* __restrict__ p) {
    int w = (blockIdx.x * blockDim.x + threadIdx.x) >> 5;
    int lane = threadIdx.x & 31;
    if (w >= BQ) return;
    const float* qr = q + (size_t)w * DIM;
    const float* pr = p + (size_t)(w * 8) * DIM;
    float s = 0.f;
    #pragma unroll 4
    for (int k = lane; k < DIM; k += 32) s = fmaf(qr[k], pr[k], s);
    #pragma unroll
    for (int o = 16; o > 0; o >>= 1) s += __shfl_down_sync(0xffffffffu, s, o);
    if (lane == 0) g_starget[w] = s;
}

// ---------------------------------------------------------------------------
// Kernel 2: 128x128 score tile per CTA via mma.sync bf16 (HMMA path).
// Epilogue: store bf16 scores + per-(row, 32col) max & rank counts. NO exp.
// grid = (128, 16), 256 threads, 3-stage cp.async pipeline.
// SMEM per stage: A 128 rows x 80B + B 128 rows x 80B = 20480B (64B data +
// 16B pad per row; stride-5 in 16B granules -> conflict-free ldmatrix).
// ---------------------------------------------------------------------------
#define STG_B 20480u
#define SMEM_BYTES (3u * STG_B)
#define NCHUNK 24     // 768 / 32

__global__ __launch_bounds__(256, 2)
void score_kernel() {
    extern __shared__ char smem[];
    const uint32_t sbase = smem_u32(smem);
    const int tid = threadIdx.x;
    const int lane = tid & 31;
    const int wid = tid >> 5;
    const int warpM = wid & 1;      // 2 warps along M (64 rows each)
    const int warpN = wid >> 1;     // 4 warps along N (32 cols each)
    const int cb = blockIdx.x;      // column block 0..127
    const int rb = blockIdx.y;      // row block 0..15

    const __nv_bfloat16* qB = g_qbf + (size_t)(rb * 128) * DIM;
    const __nv_bfloat16* pB = g_pbf + (size_t)(cb * 128) * DIM;

    float acc[4][4][4];
    #pragma unroll
    for (int mi = 0; mi < 4; mi++)
        #pragma unroll
        for (int ni = 0; ni < 4; ni++)
            #pragma unroll
            for (int r = 0; r < 4; r++) acc[mi][ni][r] = 0.f;

    // loader: 1024 x 16B transfers per stage (A 512, B 512), 4 per thread
    auto load_chunk = [&](int stg, int kt) {
        uint32_t base = sbase + (uint32_t)stg * STG_B;
        #pragma unroll
        for (int i = 0; i < 4; i++) {
            int c = tid + (i << 8);
            int isB = (c >= 512);
            int cc = c & 511;
            int row = cc >> 2, seg = cc & 3;
            const __nv_bfloat16* gp = (isB ? pB : qB) + (size_t)row * DIM + kt + seg * 8;
            uint32_t d = base + (isB ? 10240u : 0u) + (uint32_t)row * 80u + ((uint32_t)seg << 4);
            cp16(d, gp);
        }
        CP_COMMIT();
    };

    auto compute_chunk = [&](int stg) {
        uint32_t aB = sbase + (uint32_t)stg * STG_B;
        uint32_t bB = aB + 10240u;
        #pragma unroll
        for (int ks = 0; ks < 2; ks++) {
            uint32_t af_[4][4];
            #pragma unroll
            for (int mi = 0; mi < 4; mi++) {
                uint32_t addr = aB
                    + (uint32_t)((warpM * 64 + mi * 16 + (lane & 15)) * 80)
                    + (uint32_t)(ks * 32 + ((lane >> 4) << 4));
                LDSM4(af_[mi][0], af_[mi][1], af_[mi][2], af_[mi][3], addr);
            }
            uint32_t bf_[2][4];
            #pragma unroll
            for (int nj = 0; nj < 2; nj++) {
                uint32_t addr = bB
                    + (uint32_t)((warpN * 32 + nj * 16 + (lane & 7) + ((lane >> 4) << 3)) * 80)
                    + (uint32_t)(ks * 32 + (((lane >> 3) & 1) << 4));
                LDSM4(bf_[nj][0], bf_[nj][1], bf_[nj][2], bf_[nj][3], addr);
            }
            #pragma unroll
            for (int mi = 0; mi < 4; mi++)
                #pragma unroll
                for (int ni = 0; ni < 4; ni++) {
                    uint32_t b0 = bf_[ni >> 1][(ni & 1) << 1];
                    uint32_t b1 = bf_[ni >> 1][((ni & 1) << 1) + 1];
                    MMA16816(acc[mi][ni], af_[mi][0], af_[mi][1], af_[mi][2], af_[mi][3], b0, b1);
                }
        }
    };

    // 3-stage pipeline over 24 k-chunks
    load_chunk(0, 0);
    load_chunk(1, 32);
    int stC = 0, stL = 2;
    for (int c = 0; c < NCHUNK; c++) {
        if (c < NCHUNK - 1) CP_WAIT1(); else CP_WAIT0();
        __syncthreads();
        if (c < NCHUNK - 2) {
            load_chunk(stL, (c + 2) * 32);
            stL = (stL == 2) ? 0 : stL + 1;
        }
        compute_chunk(stC);
        stC = (stC == 2) ? 0 : stC + 1;
    }

    // ---- epilogue: no exp; bf16 score store + per-32col max & counts ----
    const int g = lane >> 2, q4 = lane & 3;
    #pragma unroll
    for (int mi = 0; mi < 4; mi++) {
        #pragma unroll
        for (int h = 0; h < 2; h++) {
            int row = rb * 128 + warpM * 64 + mi * 16 + h * 8 + g;
            float st = g_starget[row];
            int tcol = row * 8;
            float mx = -3.0e38f;
            int cgt = 0, ceq = 0;
            #pragma unroll
            for (int ni = 0; ni < 4; ni++) {
                #pragma unroll
                for (int j = 0; j < 2; j++) {
                    float v = acc[mi][ni][h * 2 + j];
                    int colg = cb * 128 + warpN * 32 + ni * 8 + q4 * 2 + j;
                    mx = fmaxf(mx, v);
                    if (v > st && colg != tcol) cgt++;
                    if (v == st && colg < tcol) ceq++;
                }
            }
            int cnt = cgt | (ceq << 16);
            // quad reduction (4 lanes share this row across the 32-col span)
            mx = fmaxf(mx, __shfl_xor_sync(0xffffffffu, mx, 1));
            mx = fmaxf(mx, __shfl_xor_sync(0xffffffffu, mx, 2));
            cnt += __shfl_xor_sync(0xffffffffu, cnt, 1);
            cnt += __shfl_xor_sync(0xffffffffu, cnt, 2);
            if (q4 == 0) {
                int idx = row * NB32 + cb * 4 + warpN;
                g_smax[idx] = mx;
                g_cnt[idx]  = cnt;
            }
            // bf16 score store (pairs)
            #pragma unroll
            for (int ni = 0; ni < 4; ni++) {
                __nv_bfloat162 pr =
                    __floats2bfloat162_rn(acc[mi][ni][h * 2 + 0], acc[mi][ni][h * 2 + 1]);
                int colg = cb * 128 + warpN * 32 + ni * 8 + q4 * 2;
                *(__nv_bfloat162*)(&g_sc[(size_t)row * NPAS + colg]) = pr;
            }
        }
    }
}

// ---------------------------------------------------------------------------
// Kernel 3: per row — global max, rank; re-exp only hot 32-col blocks.
// grid = BQ, 128 threads (4 slots each of 512)
// ---------------------------------------------------------------------------
__global__ void combine_kernel() {
    __shared__ float sh[128];
    __shared__ int   shi[128];
    int row = blockIdx.x;
    int t = threadIdx.x;

    float mx = -3.0e38f;
    int cnt = 0;
    #pragma unroll
    for (int i = 0; i < 4; i++) {
        int s = t + i * 128;
        mx = fmaxf(mx, g_smax[row * NB32 + s]);
        cnt += g_cnt[row * NB32 + s];
    }
    sh[t] = mx; shi[t] = cnt; __syncthreads();
    for (int o = 64; o > 0; o >>= 1) {
        if (t < o) { sh[t] = fmaxf(sh[t], sh[t + o]); shi[t] += shi[t + o]; }
        __syncthreads();
    }
    float M = sh[0];
    int call = shi[0];
    __syncthreads();

    // hot blocks: blockmax > M - 15 -> exp its 32 bf16 scores
    float ssum = 0.f;
    #pragma unroll
    for (int i = 0; i < 4; i++) {
        int s = t + i * 128;
        if (g_smax[row * NB32 + s] > M - 15.f) {
            const __nv_bfloat16* sc = g_sc + (size_t)row * NPAS + s * 32;
            #pragma unroll
            for (int j = 0; j < 32; j++)
                ssum += __expf(__bfloat162float(sc[j]) - M);
        }
    }
    sh[t] = ssum; __syncthreads();
    for (int o = 64; o > 0; o >>= 1) {
        if (t < o) sh[t] += sh[t + o];
        __syncthreads();
    }

    if (t == 0) {
        float S = sh[0];
        float rank = (float)((call & 0xffff) + (call >> 16));
        float raw = M + logf(S) - g_starget[row];
        float dr = rank - OPT_RANK;
        float w = 1.0f + ALPHA_C * expf(-(dr * dr) / (2.0f * SIGMA_C * SIGMA_C));
        g_rowloss[row] = raw * w;
    }
}

// ---------------------------------------------------------------------------
// Kernel 4: mean over rows
// ---------------------------------------------------------------------------
__global__ void finalize_kernel(float* __restrict__ out) {
    __shared__ float sh[256];
    int t = threadIdx.x;
    float s = 0.f;
    for (int i = t; i < BQ; i += 256) s += g_rowloss[i];
    sh[t] = s; __syncthreads();
    for (int o = 128; o > 0; o >>= 1) {
        if (t < o) sh[t] += sh[t + o];
        __syncthreads();
    }
    if (t == 0) out[0] = sh[0] / (float)BQ;
}

// ---------------------------------------------------------------------------
extern "C" void kernel_launch(void* const* d_in, const int* in_sizes, int n_in,
                              void* d_out, int out_size) {
    const float* q = (const float*)d_in[0];   // [2048, 768] fp32
    const float* p = (const float*)d_in[1];   // [16384, 768] fp32
    float* out = (float*)d_out;

    cudaFuncSetAttribute(score_kernel,
                         cudaFuncAttributeMaxDynamicSharedMemorySize, SMEM_BYTES);

    int nconv = ((BQ + NPAS) * DIM) / 8;
    convert_kernel<<<nconv / 256, 256>>>(q, p);
    target_kernel<<<BQ / 8, 256>>>(q, p);
    dim3 grid(NPAS / 128, BQ / 128);          // (128, 16)
    score_kernel<<<grid, 256, SMEM_BYTES>>>();
    combine_kernel<<<BQ, 128>>>();
    finalize_kernel<<<1, 256>>>(out);
}

// round 4
// speedup vs baseline: 5.4598x; 1.0633x over previous
#include <cuda_runtime.h>
#include <cuda_bf16.h>
#include <stdint.h>

// Problem constants
#define BQ 2048       // queries (rows)
#define DIM 768       // embedding dim
#define NPAS 16384    // passages (cols)
#define NB32 512      // 32-col partial blocks per row
#define ALPHA_C 2.6f
#define OPT_RANK 1.0f
#define SIGMA_C 1.8f

// Static device scratch (allocation-free)
__device__ __align__(16) __nv_bfloat16 g_qbf[BQ * DIM];
__device__ __align__(16) __nv_bfloat16 g_pbf[NPAS * DIM];
__device__ float g_starget[BQ];
__device__ __align__(16) float g_smax[BQ * NB32];
__device__ __align__(16) float g_ssum[BQ * NB32];
__device__ __align__(16) int   g_cnt[BQ * NB32];

// ---------------------------------------------------------------------------
// PTX helpers (plain sm_80+ PTX only; tcgen05 is ptxas-blocked on this build)
// ---------------------------------------------------------------------------
__device__ __forceinline__ uint32_t smem_u32(const void* p) {
    uint32_t a;
    asm("{ .reg .u64 t; cvta.to.shared.u64 t, %1; cvt.u32.u64 %0, t; }"
        : "=r"(a) : "l"(p));
    return a;
}
__device__ __forceinline__ void cp16(uint32_t dst, const void* src) {
    asm volatile("cp.async.cg.shared.global [%0], [%1], 16;"
                 :: "r"(dst), "l"(src) : "memory");
}
#define CP_COMMIT() asm volatile("cp.async.commit_group;" ::: "memory")
#define CP_WAIT1()  asm volatile("cp.async.wait_group 1;" ::: "memory")
#define CP_WAIT0()  asm volatile("cp.async.wait_group 0;" ::: "memory")

#define LDSM4(r0, r1, r2, r3, addr) \
    asm volatile("ldmatrix.sync.aligned.m8n8.x4.shared.b16 {%0,%1,%2,%3}, [%4];" \
                 : "=r"(r0), "=r"(r1), "=r"(r2), "=r"(r3) : "r"(addr))

#define MMA16816(c, a0, a1, a2, a3, b0, b1) \
    asm volatile("mma.sync.aligned.m16n8k16.row.col.f32.bf16.bf16.f32 " \
                 "{%0,%1,%2,%3}, {%4,%5,%6,%7}, {%8,%9}, {%0,%1,%2,%3};" \
                 : "+f"((c)[0]), "+f"((c)[1]), "+f"((c)[2]), "+f"((c)[3]) \
                 : "r"(a0), "r"(a1), "r"(a2), "r"(a3), "r"(b0), "r"(b1))

// MUFU-free e^x for x <= 0 (FMA-pipe only; rel err < 3e-6)
__device__ __forceinline__ float fexp(float x) {
    float t = x * 1.44269504088896f;               // log2(e) * x
    float z = t + 12582912.0f;                     // 2^23 * 1.5 magic (RN)
    int   n = __float_as_int(z) - 0x4B400000;      // nearest int
    float f = t - (float)n;                        // f in [-0.5, 0.5]
    float r = 0.0013333558f;                       // 2^f Taylor (ln2^k/k!)
    r = fmaf(r, f, 0.0096181291f);
    r = fmaf(r, f, 0.0555041087f);
    r = fmaf(r, f, 0.2402265070f);
    r = fmaf(r, f, 0.6931471806f);
    r = fmaf(r, f, 1.0f);
    r = __int_as_float(__float_as_int(r) + (n << 23));
    return (x > -87.0f) ? r : 0.0f;                // avoid exponent wrap
}

// ---------------------------------------------------------------------------
// Kernel 0: fp32 -> bf16 conversion (8 elems / thread)
// ---------------------------------------------------------------------------
__global__ void convert_kernel(const float* __restrict__ q,
                               const float* __restrict__ p) {
    size_t i = ((size_t)blockIdx.x * blockDim.x + threadIdx.x) * 8;
    const size_t nq = (size_t)BQ * DIM;
    const float* src;
    __nv_bfloat16* dst;
    if (i < nq) { src = q + i; dst = g_qbf + i; }
    else        { size_t j = i - nq; src = p + j; dst = g_pbf + j; }
    float4 a = *(const float4*)(src);
    float4 b = *(const float4*)(src + 4);
    __nv_bfloat162 v0 = __floats2bfloat162_rn(a.x, a.y);
    __nv_bfloat162 v1 = __floats2bfloat162_rn(a.z, a.w);
    __nv_bfloat162 v2 = __floats2bfloat162_rn(b.x, b.y);
    __nv_bfloat162 v3 = __floats2bfloat162_rn(b.z, b.w);
    uint4 u;
    u.x = *(uint32_t*)&v0; u.y = *(uint32_t*)&v1;
    u.z = *(uint32_t*)&v2; u.w = *(uint32_t*)&v3;
    *(uint4*)dst = u;
}

// ---------------------------------------------------------------------------
// Kernel 1: exact fp32 s_target[i] = dot(q[i], p[8i])   (one warp per row)
// ---------------------------------------------------------------------------
__global__ void target_kernel(const float* __restrict__ q,
                              const float* __restrict__ p) {
    int w = (blockIdx.x * blockDim.x + threadIdx.x) >> 5;
    int lane = threadIdx.x & 31;
    if (w >= BQ) return;
    const float* qr = q + (size_t)w * DIM;
    const float* pr = p + (size_t)(w * 8) * DIM;
    float s = 0.f;
    #pragma unroll 4
    for (int k = lane; k < DIM; k += 32) s = fmaf(qr[k], pr[k], s);
    #pragma unroll
    for (int o = 16; o > 0; o >>= 1) s += __shfl_down_sync(0xffffffffu, s, o);
    if (lane == 0) g_starget[w] = s;
}

// ---------------------------------------------------------------------------
// Kernel 2: 128x128 score tile per CTA via mma.sync bf16 (HMMA path).
// Epilogue: per-(row, 32col) block max, poly-exp partial sum, rank counts.
// No score materialization, no MUFU.
// grid = (128, 16), 256 threads, 3-stage cp.async pipeline.
// ---------------------------------------------------------------------------
#define STG_B 20480u
#define SMEM_BYTES (3u * STG_B)
#define NCHUNK 24     // 768 / 32

__global__ __launch_bounds__(256, 2)
void score_kernel() {
    extern __shared__ char smem[];
    const uint32_t sbase = smem_u32(smem);
    const int tid = threadIdx.x;
    const int lane = tid & 31;
    const int wid = tid >> 5;
    const int warpM = wid & 1;      // 2 warps along M (64 rows each)
    const int warpN = wid >> 1;     // 4 warps along N (32 cols each)
    const int cb = blockIdx.x;      // column block 0..127
    const int rb = blockIdx.y;      // row block 0..15

    const __nv_bfloat16* qB = g_qbf + (size_t)(rb * 128) * DIM;
    const __nv_bfloat16* pB = g_pbf + (size_t)(cb * 128) * DIM;

    float acc[4][4][4];
    #pragma unroll
    for (int mi = 0; mi < 4; mi++)
        #pragma unroll
        for (int ni = 0; ni < 4; ni++)
            #pragma unroll
            for (int r = 0; r < 4; r++) acc[mi][ni][r] = 0.f;

    // loader: 1024 x 16B transfers per stage (A 512, B 512), 4 per thread
    auto load_chunk = [&](int stg, int kt) {
        uint32_t base = sbase + (uint32_t)stg * STG_B;
        #pragma unroll
        for (int i = 0; i < 4; i++) {
            int c = tid + (i << 8);
            int isB = (c >= 512);
            int cc = c & 511;
            int row = cc >> 2, seg = cc & 3;
            const __nv_bfloat16* gp = (isB ? pB : qB) + (size_t)row * DIM + kt + seg * 8;
            uint32_t d = base + (isB ? 10240u : 0u) + (uint32_t)row * 80u + ((uint32_t)seg << 4);
            cp16(d, gp);
        }
        CP_COMMIT();
    };

    auto compute_chunk = [&](int stg) {
        uint32_t aB = sbase + (uint32_t)stg * STG_B;
        uint32_t bB = aB + 10240u;
        #pragma unroll
        for (int ks = 0; ks < 2; ks++) {
            uint32_t af_[4][4];
            #pragma unroll
            for (int mi = 0; mi < 4; mi++) {
                uint32_t addr = aB
                    + (uint32_t)((warpM * 64 + mi * 16 + (lane & 15)) * 80)
                    + (uint32_t)(ks * 32 + ((lane >> 4) << 4));
                LDSM4(af_[mi][0], af_[mi][1], af_[mi][2], af_[mi][3], addr);
            }
            uint32_t bf_[2][4];
            #pragma unroll
            for (int nj = 0; nj < 2; nj++) {
                uint32_t addr = bB
                    + (uint32_t)((warpN * 32 + nj * 16 + (lane & 7) + ((lane >> 4) << 3)) * 80)
                    + (uint32_t)(ks * 32 + (((lane >> 3) & 1) << 4));
                LDSM4(bf_[nj][0], bf_[nj][1], bf_[nj][2], bf_[nj][3], addr);
            }
            #pragma unroll
            for (int mi = 0; mi < 4; mi++)
                #pragma unroll
                for (int ni = 0; ni < 4; ni++) {
                    uint32_t b0 = bf_[ni >> 1][(ni & 1) << 1];
                    uint32_t b1 = bf_[ni >> 1][((ni & 1) << 1) + 1];
                    MMA16816(acc[mi][ni], af_[mi][0], af_[mi][1], af_[mi][2], af_[mi][3], b0, b1);
                }
        }
    };

    // 3-stage pipeline over 24 k-chunks
    load_chunk(0, 0);
    load_chunk(1, 32);
    int stC = 0, stL = 2;
    for (int c = 0; c < NCHUNK; c++) {
        if (c < NCHUNK - 1) CP_WAIT1(); else CP_WAIT0();
        __syncthreads();
        if (c < NCHUNK - 2) {
            load_chunk(stL, (c + 2) * 32);
            stL = (stL == 2) ? 0 : stL + 1;
        }
        compute_chunk(stC);
        stC = (stC == 2) ? 0 : stC + 1;
    }

    // ---- epilogue: block max, poly-exp sum, rank counts (no stores of scores)
    const int g = lane >> 2, q4 = lane & 3;
    #pragma unroll
    for (int mi = 0; mi < 4; mi++) {
        #pragma unroll
        for (int h = 0; h < 2; h++) {
            int row = rb * 128 + warpM * 64 + mi * 16 + h * 8 + g;
            float st = g_starget[row];
            int tcol = row * 8;
            float v[8];
            #pragma unroll
            for (int ni = 0; ni < 4; ni++) {
                v[ni * 2 + 0] = acc[mi][ni][h * 2 + 0];
                v[ni * 2 + 1] = acc[mi][ni][h * 2 + 1];
            }
            float mx = v[0];
            #pragma unroll
            for (int j = 1; j < 8; j++) mx = fmaxf(mx, v[j]);
            int cgt = 0, ceq = 0;
            #pragma unroll
            for (int j = 0; j < 8; j++) {
                int colg = cb * 128 + warpN * 32 + (j >> 1) * 8 + q4 * 2 + (j & 1);
                if (v[j] > st && colg != tcol) cgt++;
                if (v[j] == st && colg < tcol) ceq++;
            }
            int cnt = cgt | (ceq << 16);
            // quad reduction: 4 lanes cover this row's 32-col block
            mx = fmaxf(mx, __shfl_xor_sync(0xffffffffu, mx, 1));
            mx = fmaxf(mx, __shfl_xor_sync(0xffffffffu, mx, 2));
            cnt += __shfl_xor_sync(0xffffffffu, cnt, 1);
            cnt += __shfl_xor_sync(0xffffffffu, cnt, 2);
            float s = 0.f;
            #pragma unroll
            for (int j = 0; j < 8; j++) s += fexp(v[j] - mx);
            s += __shfl_xor_sync(0xffffffffu, s, 1);
            s += __shfl_xor_sync(0xffffffffu, s, 2);
            if (q4 == 0) {
                int idx = row * NB32 + cb * 4 + warpN;
                g_smax[idx] = mx;
                g_ssum[idx] = s;
                g_cnt[idx]  = cnt;
            }
        }
    }
}

// ---------------------------------------------------------------------------
// Kernel 3a: zero the output accumulator
// ---------------------------------------------------------------------------
__global__ void zero_kernel(float* __restrict__ out) { out[0] = 0.f; }

// ---------------------------------------------------------------------------
// Kernel 3b: warp-per-row combine: merge 512 block partials -> row loss,
// block-accumulate, one atomicAdd per block. grid = 256, block = 256.
// ---------------------------------------------------------------------------
__global__ __launch_bounds__(256)
void combine_kernel(float* __restrict__ out) {
    __shared__ float sh[8];
    const int lane = threadIdx.x & 31;
    const int warp = threadIdx.x >> 5;
    const int row = blockIdx.x * 8 + warp;

    const float4* smax4 = (const float4*)(g_smax + (size_t)row * NB32);
    const float4* ssum4 = (const float4*)(g_ssum + (size_t)row * NB32);
    const int4*   cnt4  = (const int4*)  (g_cnt  + (size_t)row * NB32);

    // pass 1: global row max + rank counts
    float mx = -3.0e38f;
    int cnt = 0;
    #pragma unroll
    for (int k = 0; k < 4; k++) {
        float4 m = smax4[k * 32 + lane];
        int4   c = cnt4 [k * 32 + lane];
        mx = fmaxf(fmaxf(fmaxf(mx, m.x), fmaxf(m.y, m.z)), m.w);
        cnt += c.x + c.y + c.z + c.w;
    }
    #pragma unroll
    for (int o = 16; o > 0; o >>= 1) {
        mx = fmaxf(mx, __shfl_xor_sync(0xffffffffu, mx, o));
        cnt += __shfl_xor_sync(0xffffffffu, cnt, o);
    }

    // pass 2: S = sum_b ssum_b * exp(smax_b - M)
    float S = 0.f;
    #pragma unroll
    for (int k = 0; k < 4; k++) {
        float4 m = smax4[k * 32 + lane];
        float4 s = ssum4[k * 32 + lane];
        S += s.x * fexp(m.x - mx) + s.y * fexp(m.y - mx)
           + s.z * fexp(m.z - mx) + s.w * fexp(m.w - mx);
    }
    #pragma unroll
    for (int o = 16; o > 0; o >>= 1) S += __shfl_xor_sync(0xffffffffu, S, o);

    if (lane == 0) {
        float rank = (float)((cnt & 0xffff) + (cnt >> 16));
        float raw = mx + logf(S) - g_starget[row];
        float dr = rank - OPT_RANK;
        float w = 1.0f + ALPHA_C * expf(-(dr * dr) / (2.0f * SIGMA_C * SIGMA_C));
        sh[warp] = raw * w;
    }
    __syncthreads();
    if (threadIdx.x == 0) {
        float t = 0.f;
        #pragma unroll
        for (int i = 0; i < 8; i++) t += sh[i];
        atomicAdd(out, t * (1.0f / (float)BQ));
    }
}

// ---------------------------------------------------------------------------
extern "C" void kernel_launch(void* const* d_in, const int* in_sizes, int n_in,
                              void* d_out, int out_size) {
    const float* q = (const float*)d_in[0];   // [2048, 768] fp32
    const float* p = (const float*)d_in[1];   // [16384, 768] fp32
    float* out = (float*)d_out;

    cudaFuncSetAttribute(score_kernel,
                         cudaFuncAttributeMaxDynamicSharedMemorySize, SMEM_BYTES);

    int nconv = ((BQ + NPAS) * DIM) / 8;
    convert_kernel<<<nconv / 256, 256>>>(q, p);
    target_kernel<<<BQ / 8, 256>>>(q, p);
    dim3 grid(NPAS / 128, BQ / 128);          // (128, 16)
    score_kernel<<<grid, 256, SMEM_BYTES>>>();
    zero_kernel<<<1, 1>>>(out);
    combine_kernel<<<BQ / 8, 256>>>(out);
}